// round 1
// baseline (speedup 1.0000x reference)
#include <cuda_runtime.h>
#include <math.h>

#define NB     16      // B*D flattened batch
#define C_IN   128
#define HH_    64
#define WW_    64
#define HW     4096
#define OC_OFF 72      // 2*K*GROUPS offset channels
#define OG     4
#define CG     32      // channels per offset group
#define OUT_C  128
#define KK     9

// ---------------- static device scratch (allocation-free rule) ----------------
__device__ float g_offset[NB * OC_OFF * HW];        // 18.9 MB
__device__ float g_tmp   [NB * OUT_C  * HW];        // 33.5 MB  (pre-norm deform output)
__device__ float g_woff_t[C_IN * KK * OC_OFF];      // [c][tap][oc]
__device__ float g_wdc_t [OG * KK * CG * CG];       // [g][k][c][o]

// ---------------- kernel 0: weight transposes ----------------
__global__ void prep_kernel(const float* __restrict__ w_off,
                            const float* __restrict__ w_dc) {
    int idx = blockIdx.x * blockDim.x + threadIdx.x;
    if (idx < C_IN * KK * OC_OFF) {
        int c   = idx / (KK * OC_OFF);
        int tap = (idx / OC_OFF) % KK;
        int oc  = idx % OC_OFF;
        g_woff_t[idx] = w_off[(oc * C_IN + c) * KK + tap];
    }
    if (idx < OG * KK * CG * CG) {
        int g = idx / (KK * CG * CG);
        int k = (idx / (CG * CG)) % KK;
        int c = (idx / CG) % CG;
        int o = idx % CG;
        g_wdc_t[idx] = w_dc[((g * CG + o) * CG + c) * KK + k];
    }
}

// ---------------- kernel 1: offset conv (3x3, pad 1, C=128 -> 72) ----------------
// Block: (h2, n) covers 2 output rows (128 px), all 72 out channels.
// 288 threads: ocg = tid/32 -> 8 out channels, lane = tid%32 -> 4 px interleaved
// (p = lane + 32*i). smem x tile [8c][4rows][66cols], weights [8c][9tap][72oc].
#define OCONV_THREADS 288
__global__ __launch_bounds__(OCONV_THREADS)
void offset_conv_kernel(const float* __restrict__ x,
                        const float* __restrict__ b_off) {
    __shared__ float xs[8 * 4 * 66];       // 8.4 KB
    __shared__ float ws[8 * KK * OC_OFF];  // 20.7 KB

    const int h2  = blockIdx.x;            // 0..31 (pairs of rows)
    const int n   = blockIdx.y;            // 0..15
    const int b   = n >> 3, d = n & 7;
    const int tid = threadIdx.x;
    const int ocg = tid >> 5;              // 0..8
    const int lane = tid & 31;
    const int oc0 = ocg * 8;

    float acc[8][4];
#pragma unroll
    for (int j = 0; j < 8; j++)
#pragma unroll
        for (int i = 0; i < 4; i++) acc[j][i] = 0.f;

    // x element (b,c,d,h,w) = x[(((b*128+c)*8+d)*4096 + h*64 + w]
    const float* xn = x + (((size_t)b * C_IN) * 8 + d) * HW;

    for (int c0 = 0; c0 < C_IN; c0 += 8) {
        // load input tile: rows h2*2-1 .. h2*2+2, cols -1..64 (zero pad)
        for (int i = tid; i < 8 * 4 * 66; i += OCONV_THREADS) {
            int c   = i / 264;
            int rem = i - c * 264;
            int r   = rem / 66;
            int col = rem - r * 66;
            int hin = h2 * 2 - 1 + r;
            int win = col - 1;
            float v = 0.f;
            if (hin >= 0 && hin < HH_ && win >= 0 && win < WW_)
                v = xn[(size_t)(c0 + c) * (8 * HW) + hin * WW_ + win];
            xs[i] = v;
        }
        // load weight chunk (already [c][tap][oc])
        for (int i = tid; i < 8 * KK * OC_OFF; i += OCONV_THREADS)
            ws[i] = g_woff_t[c0 * (KK * OC_OFF) + i];
        __syncthreads();

#pragma unroll
        for (int c = 0; c < 8; c++) {
#pragma unroll
            for (int tap = 0; tap < 9; tap++) {
                const int ky = tap / 3, kx = tap % 3;
                float xv[4];
#pragma unroll
                for (int i = 0; i < 4; i++) {
                    int hh = i >> 1;
                    int w  = lane + ((i & 1) << 5);
                    xv[i] = xs[(c * 4 + hh + ky) * 66 + w + kx];
                }
                float wv[8];
#pragma unroll
                for (int j = 0; j < 8; j++)
                    wv[j] = ws[(c * 9 + tap) * OC_OFF + oc0 + j];
#pragma unroll
                for (int j = 0; j < 8; j++)
#pragma unroll
                    for (int i = 0; i < 4; i++)
                        acc[j][i] = fmaf(wv[j], xv[i], acc[j][i]);
            }
        }
        __syncthreads();
    }

    float* outp = g_offset + (size_t)n * (OC_OFF * HW) + h2 * 128;
#pragma unroll
    for (int j = 0; j < 8; j++) {
        float bb = b_off[oc0 + j];
#pragma unroll
        for (int i = 0; i < 4; i++)
            outp[(size_t)(oc0 + j) * HW + lane + 32 * i] = acc[j][i] + bb;
    }
}

// ---------------- kernel 2: deformable conv ----------------
// Block: (h2, g, n) -> 2 output rows (128 px), one offset group (32 in-ch, 32 out-ch).
// Phase A (per tap k): each of 128 threads owns one pixel, bilinear-samples 32 channels
// into smem samp[c][p]. Phase B: GEMM 32oc x 128px x 32c with wdc in smem.
#define DEF_THREADS 128
#define DEF_SMEM_FLOATS (KK * CG * CG + CG * 128)   // 9216 + 4096
__global__ __launch_bounds__(DEF_THREADS)
void deform_kernel(const float* __restrict__ x,
                   const float* __restrict__ b_dc) {
    extern __shared__ float sm[];
    float* wdc_s = sm;           // [9][32][32]
    float* samp  = sm + KK * CG * CG; // [32][128]

    const int h2 = blockIdx.x;   // 0..31
    const int g  = blockIdx.y;   // 0..3
    const int n  = blockIdx.z;   // 0..15
    const int b  = n >> 3, d = n & 7;
    const int tid = threadIdx.x;

    for (int i = tid; i < KK * CG * CG; i += DEF_THREADS)
        wdc_s[i] = g_wdc_t[g * (KK * CG * CG) + i];

    // sampler coordinates (one pixel per thread)
    const int sp = tid;               // 0..127
    const int sh = h2 * 2 + (sp >> 6);
    const int sw = sp & 63;
    const float* xbase = x + (((size_t)b * C_IN + g * CG) * 8 + d) * HW;
    const float* offb  = g_offset + (size_t)n * (OC_OFF * HW)
                       + (size_t)(g * KK * 2) * HW + sh * WW_ + sw;

    // GEMM coordinates
    const int ogrp = tid >> 5;        // warp id -> 8 out channels
    const int o0   = ogrp * 8;
    const int lane = tid & 31;

    float acc[8][4];
#pragma unroll
    for (int j = 0; j < 8; j++)
#pragma unroll
        for (int i = 0; i < 4; i++) acc[j][i] = 0.f;

    __syncthreads();

    for (int k = 0; k < KK; k++) {
        // ---- phase A: bilinear sampling ----
        float dy = offb[(size_t)(2 * k) * HW];
        float dx = offb[(size_t)(2 * k + 1) * HW];
        int ky = k / 3, kx = k % 3;
        float py = dy + (float)(sh + ky - 1);
        float px = dx + (float)(sw + kx - 1);
        float y0f = floorf(py), x0f = floorf(px);
        int   y0 = (int)y0f,   x0 = (int)x0f;
        float ly = py - y0f, lx = px - x0f;
        float hy = 1.f - ly, hx = 1.f - lx;
        bool vy0 = (y0 >= 0)  && (y0 < HH_);
        bool vy1 = (y0 >= -1) && (y0 < HH_ - 1);
        bool vx0 = (x0 >= 0)  && (x0 < WW_);
        bool vx1 = (x0 >= -1) && (x0 < WW_ - 1);
        int yc0 = min(max(y0, 0), HH_ - 1), yc1 = min(max(y0 + 1, 0), HH_ - 1);
        int xc0 = min(max(x0, 0), WW_ - 1), xc1 = min(max(x0 + 1, 0), WW_ - 1);
        float w00 = hy * hx * (float)(vy0 && vx0);
        float w01 = hy * lx * (float)(vy0 && vx1);
        float w10 = ly * hx * (float)(vy1 && vx0);
        float w11 = ly * lx * (float)(vy1 && vx1);
        int i00 = yc0 * WW_ + xc0, i01 = yc0 * WW_ + xc1;
        int i10 = yc1 * WW_ + xc0, i11 = yc1 * WW_ + xc1;
#pragma unroll 8
        for (int c = 0; c < CG; c++) {
            const float* xp = xbase + (size_t)c * (8 * HW);
            float v = w00 * __ldg(xp + i00) + w01 * __ldg(xp + i01)
                    + w10 * __ldg(xp + i10) + w11 * __ldg(xp + i11);
            samp[c * 128 + sp] = v;
        }
        __syncthreads();
        // ---- phase B: GEMM accumulate ----
#pragma unroll
        for (int c = 0; c < CG; c++) {
            float sv[4];
#pragma unroll
            for (int i = 0; i < 4; i++) sv[i] = samp[c * 128 + lane + 32 * i];
            float wv[8];
#pragma unroll
            for (int j = 0; j < 8; j++)
                wv[j] = wdc_s[(k * CG + c) * CG + o0 + j];
#pragma unroll
            for (int j = 0; j < 8; j++)
#pragma unroll
                for (int i = 0; i < 4; i++)
                    acc[j][i] = fmaf(wv[j], sv[i], acc[j][i]);
        }
        __syncthreads();
    }

    float* outp = g_tmp + ((size_t)n * OUT_C + g * CG + o0) * HW + h2 * 128;
#pragma unroll
    for (int j = 0; j < 8; j++) {
        float bb = b_dc[g * CG + o0 + j];
#pragma unroll
        for (int i = 0; i < 4; i++)
            outp[(size_t)j * HW + lane + 32 * i] = acc[j][i] + bb;
    }
}

// ---------------- kernel 3: instance norm + exact GELU + layout transpose ----------------
// Block per (n, c): deterministic in-block reduction over the 4096-pixel plane.
__global__ __launch_bounds__(256)
void finalize_kernel(float* __restrict__ out) {
    const int c = blockIdx.x;   // 0..127
    const int n = blockIdx.y;   // 0..15
    const int b = n >> 3, d = n & 7;
    const int tid = threadIdx.x;

    const float* tp = g_tmp + ((size_t)n * OUT_C + c) * HW;
    float v[16];
    float s = 0.f, ss = 0.f;
#pragma unroll
    for (int i = 0; i < 16; i++) {
        float t = tp[tid + 256 * i];
        v[i] = t; s += t; ss += t * t;
    }
#pragma unroll
    for (int o = 16; o > 0; o >>= 1) {
        s  += __shfl_down_sync(0xffffffffu, s,  o);
        ss += __shfl_down_sync(0xffffffffu, ss, o);
    }
    __shared__ float s1[8], s2[8];
    __shared__ float mu_s, inv_s;
    int wid = tid >> 5, lane = tid & 31;
    if (lane == 0) { s1[wid] = s; s2[wid] = ss; }
    __syncthreads();
    if (tid == 0) {
        float ts = 0.f, tss = 0.f;
#pragma unroll
        for (int i = 0; i < 8; i++) { ts += s1[i]; tss += s2[i]; }
        float mu  = ts * (1.f / 4096.f);
        float var = tss * (1.f / 4096.f) - mu * mu;
        mu_s  = mu;
        inv_s = rsqrtf(var + 1e-5f);
    }
    __syncthreads();
    float mu = mu_s, inv = inv_s;

    float* op = out + (((size_t)b * OUT_C + c) * 8 + d) * HW;
#pragma unroll
    for (int i = 0; i < 16; i++) {
        float t = (v[i] - mu) * inv;
        op[tid + 256 * i] = 0.5f * t * (1.f + erff(t * 0.70710678118654752f));
    }
}

// ---------------- launcher ----------------
extern "C" void kernel_launch(void* const* d_in, const int* in_sizes, int n_in,
                              void* d_out, int out_size) {
    (void)in_sizes; (void)n_in; (void)out_size;
    const float* x     = (const float*)d_in[0];
    const float* w_off = (const float*)d_in[1];
    const float* b_off = (const float*)d_in[2];
    const float* w_dc  = (const float*)d_in[3];
    const float* b_dc  = (const float*)d_in[4];
    float* out = (float*)d_out;

    prep_kernel<<<(C_IN * KK * OC_OFF + 255) / 256, 256>>>(w_off, w_dc);

    dim3 gco(32, NB);
    offset_conv_kernel<<<gco, OCONV_THREADS>>>(x, b_off);

    static int smem_set = 0;
    if (!smem_set) {
        cudaFuncSetAttribute(deform_kernel,
                             cudaFuncAttributeMaxDynamicSharedMemorySize,
                             DEF_SMEM_FLOATS * sizeof(float));
        smem_set = 1;
    }
    dim3 gdf(32, OG, NB);
    deform_kernel<<<gdf, DEF_THREADS, DEF_SMEM_FLOATS * sizeof(float)>>>(x, b_dc);

    dim3 gfn(OUT_C, NB);
    finalize_kernel<<<gfn, 256>>>(out);
}

// round 2
// speedup vs baseline: 1.0832x; 1.0832x over previous
#include <cuda_runtime.h>
#include <math.h>

#define NB     16      // B*D flattened batch
#define C_IN   128
#define HH_    64
#define WW_    64
#define HW     4096
#define OC_OFF 72      // 2*K*GROUPS offset channels
#define OG     4
#define CG     32      // channels per offset group
#define OUT_C  128
#define KK     9

typedef unsigned long long u64;

// ---- packed f32x2 helpers (Blackwell FFMA2 path) ----
__device__ __forceinline__ u64 pack2(float lo, float hi) {
    u64 r;
    asm("mov.b64 %0, {%1, %2};" : "=l"(r) : "f"(lo), "f"(hi));
    return r;
}
__device__ __forceinline__ void fma2(u64& d, u64 a, u64 b) {
    asm("fma.rn.f32x2 %0, %1, %2, %0;" : "+l"(d) : "l"(a), "l"(b));
}
__device__ __forceinline__ void unpack2(u64 v, float& lo, float& hi) {
    asm("mov.b64 {%0, %1}, %2;" : "=f"(lo), "=f"(hi) : "l"(v));
}

// ---------------- static device scratch (allocation-free rule) ----------------
__device__ float g_offset[NB * OC_OFF * HW];        // 18.9 MB
__device__ float g_tmp   [NB * OUT_C  * HW];        // 33.5 MB  (pre-norm deform output)
__device__ float g_woff_t[C_IN * KK * OC_OFF];      // [c][tap][oc]
__device__ float g_wdc_t [OG * KK * CG * CG];       // [g][k][c][o]

// ---------------- kernel 0: weight transposes ----------------
__global__ void prep_kernel(const float* __restrict__ w_off,
                            const float* __restrict__ w_dc) {
    int idx = blockIdx.x * blockDim.x + threadIdx.x;
    if (idx < C_IN * KK * OC_OFF) {
        int c   = idx / (KK * OC_OFF);
        int tap = (idx / OC_OFF) % KK;
        int oc  = idx % OC_OFF;
        g_woff_t[idx] = w_off[(oc * C_IN + c) * KK + tap];
    }
    if (idx < OG * KK * CG * CG) {
        int g = idx / (KK * CG * CG);
        int k = (idx / (CG * CG)) % KK;
        int c = (idx / CG) % CG;
        int o = idx % CG;
        g_wdc_t[idx] = w_dc[((g * CG + o) * CG + c) * KK + k];
    }
}

// ---------------- kernel 1: offset conv (3x3, pad 1, C=128 -> 72) ----------------
// Block: (h2, n) covers 2 output rows (128 px), all 72 out channels.
// 288 threads: ocg = tid/32 -> 8 out channels, lane = tid%32 -> 4 px interleaved.
// Inner loop uses FFMA2: oc paired (adjacent in ws -> one LDS.64), px scalar dup'd.
#define OCONV_THREADS 288
__global__ __launch_bounds__(OCONV_THREADS)
void offset_conv_kernel(const float* __restrict__ x,
                        const float* __restrict__ b_off) {
    __shared__ __align__(16) float xs[8 * 4 * 66];       // 8.4 KB
    __shared__ __align__(16) float ws[8 * KK * OC_OFF];  // 20.7 KB

    const int h2  = blockIdx.x;            // 0..31 (pairs of rows)
    const int n   = blockIdx.y;            // 0..15
    const int b   = n >> 3, d = n & 7;
    const int tid = threadIdx.x;
    const int ocg = tid >> 5;              // 0..8
    const int lane = tid & 31;
    const int oc0 = ocg * 8;

    u64 acc2[4][4];                        // [oc-pair][px], each holds 2 oc
#pragma unroll
    for (int jp = 0; jp < 4; jp++)
#pragma unroll
        for (int i = 0; i < 4; i++) acc2[jp][i] = 0ull;

    const float* xn = x + (((size_t)b * C_IN) * 8 + d) * HW;

    for (int c0 = 0; c0 < C_IN; c0 += 8) {
        // load input tile: rows h2*2-1 .. h2*2+2, cols -1..64 (zero pad)
        for (int i = tid; i < 8 * 4 * 66; i += OCONV_THREADS) {
            int c   = i / 264;
            int rem = i - c * 264;
            int r   = rem / 66;
            int col = rem - r * 66;
            int hin = h2 * 2 - 1 + r;
            int win = col - 1;
            float v = 0.f;
            if (hin >= 0 && hin < HH_ && win >= 0 && win < WW_)
                v = xn[(size_t)(c0 + c) * (8 * HW) + hin * WW_ + win];
            xs[i] = v;
        }
        for (int i = tid; i < 8 * KK * OC_OFF; i += OCONV_THREADS)
            ws[i] = g_woff_t[c0 * (KK * OC_OFF) + i];
        __syncthreads();

#pragma unroll
        for (int c = 0; c < 8; c++) {
#pragma unroll
            for (int tap = 0; tap < 9; tap++) {
                const int ky = tap / 3, kx = tap % 3;
                u64 xv2[4];
#pragma unroll
                for (int i = 0; i < 4; i++) {
                    int hh = i >> 1;
                    int w  = lane + ((i & 1) << 5);
                    float xv = xs[(c * 4 + hh + ky) * 66 + w + kx];
                    xv2[i] = pack2(xv, xv);
                }
                const float* wp = &ws[(c * 9 + tap) * OC_OFF + oc0];
                u64 wv2[4];
#pragma unroll
                for (int jp = 0; jp < 4; jp++)
                    wv2[jp] = *reinterpret_cast<const u64*>(wp + 2 * jp);
#pragma unroll
                for (int jp = 0; jp < 4; jp++)
#pragma unroll
                    for (int i = 0; i < 4; i++)
                        fma2(acc2[jp][i], wv2[jp], xv2[i]);
            }
        }
        __syncthreads();
    }

    float* outp = g_offset + (size_t)n * (OC_OFF * HW) + h2 * 128;
#pragma unroll
    for (int jp = 0; jp < 4; jp++) {
        float b0 = b_off[oc0 + 2 * jp];
        float b1 = b_off[oc0 + 2 * jp + 1];
#pragma unroll
        for (int i = 0; i < 4; i++) {
            float lo, hi;
            unpack2(acc2[jp][i], lo, hi);
            int p = lane + 32 * i;
            outp[(size_t)(oc0 + 2 * jp)     * HW + p] = lo + b0;
            outp[(size_t)(oc0 + 2 * jp + 1) * HW + p] = hi + b1;
        }
    }
}

// ---------------- kernel 2: deformable conv ----------------
// Block: (h2, g, n) -> 2 output rows (128 px), one offset group (32 in-ch, 32 out-ch).
// Phase A (per tap k): each of 128 threads bilinear-samples 32 channels into smem.
// Phase B: GEMM 32oc x 128px x 32c with FFMA2 (oc paired via LDS.64).
#define DEF_THREADS 128
#define DEF_SMEM_FLOATS (KK * CG * CG + CG * 128)   // 9216 + 4096
__global__ __launch_bounds__(DEF_THREADS)
void deform_kernel(const float* __restrict__ x,
                   const float* __restrict__ b_dc) {
    extern __shared__ __align__(16) float sm[];
    float* wdc_s = sm;                 // [9][32][32]
    float* samp  = sm + KK * CG * CG;  // [32][128]

    const int h2 = blockIdx.x;   // 0..31
    const int g  = blockIdx.y;   // 0..3
    const int n  = blockIdx.z;   // 0..15
    const int b  = n >> 3, d = n & 7;
    const int tid = threadIdx.x;

    for (int i = tid; i < KK * CG * CG; i += DEF_THREADS)
        wdc_s[i] = g_wdc_t[g * (KK * CG * CG) + i];

    // sampler coordinates (one pixel per thread)
    const int sp = tid;               // 0..127
    const int sh = h2 * 2 + (sp >> 6);
    const int sw = sp & 63;
    const float* xbase = x + (((size_t)b * C_IN + g * CG) * 8 + d) * HW;
    const float* offb  = g_offset + (size_t)n * (OC_OFF * HW)
                       + (size_t)(g * KK * 2) * HW + sh * WW_ + sw;

    // GEMM coordinates
    const int ogrp = tid >> 5;        // warp id -> 8 out channels
    const int o0   = ogrp * 8;
    const int lane = tid & 31;

    u64 acc2[4][4];
#pragma unroll
    for (int jp = 0; jp < 4; jp++)
#pragma unroll
        for (int i = 0; i < 4; i++) acc2[jp][i] = 0ull;

    __syncthreads();

    for (int k = 0; k < KK; k++) {
        // ---- phase A: bilinear sampling ----
        float dy = offb[(size_t)(2 * k) * HW];
        float dx = offb[(size_t)(2 * k + 1) * HW];
        int ky = k / 3, kx = k % 3;
        float py = dy + (float)(sh + ky - 1);
        float px = dx + (float)(sw + kx - 1);
        float y0f = floorf(py), x0f = floorf(px);
        int   y0 = (int)y0f,   x0 = (int)x0f;
        float ly = py - y0f, lx = px - x0f;
        float hy = 1.f - ly, hx = 1.f - lx;
        bool vy0 = (y0 >= 0)  && (y0 < HH_);
        bool vy1 = (y0 >= -1) && (y0 < HH_ - 1);
        bool vx0 = (x0 >= 0)  && (x0 < WW_);
        bool vx1 = (x0 >= -1) && (x0 < WW_ - 1);
        int yc0 = min(max(y0, 0), HH_ - 1), yc1 = min(max(y0 + 1, 0), HH_ - 1);
        int xc0 = min(max(x0, 0), WW_ - 1), xc1 = min(max(x0 + 1, 0), WW_ - 1);
        float w00 = hy * hx * (float)(vy0 && vx0);
        float w01 = hy * lx * (float)(vy0 && vx1);
        float w10 = ly * hx * (float)(vy1 && vx0);
        float w11 = ly * lx * (float)(vy1 && vx1);
        int i00 = yc0 * WW_ + xc0, i01 = yc0 * WW_ + xc1;
        int i10 = yc1 * WW_ + xc0, i11 = yc1 * WW_ + xc1;
#pragma unroll 8
        for (int c = 0; c < CG; c++) {
            const float* xp = xbase + (size_t)c * (8 * HW);
            float v = w00 * __ldg(xp + i00) + w01 * __ldg(xp + i01)
                    + w10 * __ldg(xp + i10) + w11 * __ldg(xp + i11);
            samp[c * 128 + sp] = v;
        }
        __syncthreads();
        // ---- phase B: GEMM accumulate (FFMA2) ----
#pragma unroll
        for (int c = 0; c < CG; c++) {
            u64 sv2[4];
#pragma unroll
            for (int i = 0; i < 4; i++) {
                float sv = samp[c * 128 + lane + 32 * i];
                sv2[i] = pack2(sv, sv);
            }
            const float* wp = &wdc_s[(k * CG + c) * CG + o0];
            u64 wv2[4];
#pragma unroll
            for (int jp = 0; jp < 4; jp++)
                wv2[jp] = *reinterpret_cast<const u64*>(wp + 2 * jp);
#pragma unroll
            for (int jp = 0; jp < 4; jp++)
#pragma unroll
                for (int i = 0; i < 4; i++)
                    fma2(acc2[jp][i], wv2[jp], sv2[i]);
        }
        __syncthreads();
    }

    float* outp = g_tmp + ((size_t)n * OUT_C + g * CG + o0) * HW + h2 * 128;
#pragma unroll
    for (int jp = 0; jp < 4; jp++) {
        float b0 = b_dc[g * CG + o0 + 2 * jp];
        float b1 = b_dc[g * CG + o0 + 2 * jp + 1];
#pragma unroll
        for (int i = 0; i < 4; i++) {
            float lo, hi;
            unpack2(acc2[jp][i], lo, hi);
            int p = lane + 32 * i;
            outp[(size_t)(2 * jp)     * HW + p] = lo + b0;
            outp[(size_t)(2 * jp + 1) * HW + p] = hi + b1;
        }
    }
}

// ---------------- kernel 3: instance norm + exact GELU + layout transpose ----------------
__global__ __launch_bounds__(256)
void finalize_kernel(float* __restrict__ out) {
    const int c = blockIdx.x;   // 0..127
    const int n = blockIdx.y;   // 0..15
    const int b = n >> 3, d = n & 7;
    const int tid = threadIdx.x;

    const float* tp = g_tmp + ((size_t)n * OUT_C + c) * HW;
    float v[16];
    float s = 0.f, ss = 0.f;
#pragma unroll
    for (int i = 0; i < 16; i++) {
        float t = tp[tid + 256 * i];
        v[i] = t; s += t; ss += t * t;
    }
#pragma unroll
    for (int o = 16; o > 0; o >>= 1) {
        s  += __shfl_down_sync(0xffffffffu, s,  o);
        ss += __shfl_down_sync(0xffffffffu, ss, o);
    }
    __shared__ float s1[8], s2[8];
    __shared__ float mu_s, inv_s;
    int wid = tid >> 5, lane = tid & 31;
    if (lane == 0) { s1[wid] = s; s2[wid] = ss; }
    __syncthreads();
    if (tid == 0) {
        float ts = 0.f, tss = 0.f;
#pragma unroll
        for (int i = 0; i < 8; i++) { ts += s1[i]; tss += s2[i]; }
        float mu  = ts * (1.f / 4096.f);
        float var = tss * (1.f / 4096.f) - mu * mu;
        mu_s  = mu;
        inv_s = rsqrtf(var + 1e-5f);
    }
    __syncthreads();
    float mu = mu_s, inv = inv_s;

    float* op = out + (((size_t)b * OUT_C + c) * 8 + d) * HW;
#pragma unroll
    for (int i = 0; i < 16; i++) {
        float t = (v[i] - mu) * inv;
        op[tid + 256 * i] = 0.5f * t * (1.f + erff(t * 0.70710678118654752f));
    }
}

// ---------------- launcher ----------------
extern "C" void kernel_launch(void* const* d_in, const int* in_sizes, int n_in,
                              void* d_out, int out_size) {
    (void)in_sizes; (void)n_in; (void)out_size;
    const float* x     = (const float*)d_in[0];
    const float* w_off = (const float*)d_in[1];
    const float* b_off = (const float*)d_in[2];
    const float* w_dc  = (const float*)d_in[3];
    const float* b_dc  = (const float*)d_in[4];
    float* out = (float*)d_out;

    prep_kernel<<<(C_IN * KK * OC_OFF + 255) / 256, 256>>>(w_off, w_dc);

    dim3 gco(32, NB);
    offset_conv_kernel<<<gco, OCONV_THREADS>>>(x, b_off);

    static int smem_set = 0;
    if (!smem_set) {
        cudaFuncSetAttribute(deform_kernel,
                             cudaFuncAttributeMaxDynamicSharedMemorySize,
                             DEF_SMEM_FLOATS * sizeof(float));
        smem_set = 1;
    }
    dim3 gdf(32, OG, NB);
    deform_kernel<<<gdf, DEF_THREADS, DEF_SMEM_FLOATS * sizeof(float)>>>(x, b_dc);

    dim3 gfn(OUT_C, NB);
    finalize_kernel<<<gfn, 256>>>(out);
}

// round 4
// speedup vs baseline: 1.3348x; 1.2322x over previous
#include <cuda_runtime.h>
#include <math.h>
#include <stdint.h>

#define NB     16
#define C_IN   128
#define HH_    64
#define WW_    64
#define HW     4096
#define OC_OFF 72
#define OG     4
#define CG     32
#define OUT_C  128
#define KK     9

typedef unsigned long long u64;

// ---- packed f32x2 helpers (deform conv path) ----
__device__ __forceinline__ u64 pack2(float lo, float hi) {
    u64 r; asm("mov.b64 %0, {%1, %2};" : "=l"(r) : "f"(lo), "f"(hi)); return r;
}
__device__ __forceinline__ void fma2(u64& d, u64 a, u64 b) {
    asm("fma.rn.f32x2 %0, %1, %2, %0;" : "+l"(d) : "l"(a), "l"(b));
}
__device__ __forceinline__ void unpack2(u64 v, float& lo, float& hi) {
    asm("mov.b64 {%0, %1}, %2;" : "=f"(lo), "=f"(hi) : "l"(v));
}

// ---- tf32 mma helpers (base sm_100 ISA, no 'a' features) ----
__device__ __forceinline__ uint32_t f2tf32(float v) {
    uint32_t r; asm("cvt.rna.tf32.f32 %0, %1;" : "=r"(r) : "f"(v)); return r;
}
__device__ __forceinline__ void mma_tf32(float* d, const uint32_t* a,
                                         uint32_t b0, uint32_t b1) {
    asm volatile(
        "mma.sync.aligned.m16n8k8.row.col.f32.tf32.tf32.f32 "
        "{%0,%1,%2,%3},{%4,%5,%6,%7},{%8,%9},{%0,%1,%2,%3};"
        : "+f"(d[0]), "+f"(d[1]), "+f"(d[2]), "+f"(d[3])
        : "r"(a[0]), "r"(a[1]), "r"(a[2]), "r"(a[3]), "r"(b0), "r"(b1));
}

// ================= static device scratch =================
__device__ float g_offset[NB * OC_OFF * HW];
__device__ float g_tmp   [NB * OUT_C  * HW];
__device__ float g_wdc_t [OG * KK * CG * CG];
// offset conv weights, tf32 hi/lo split: [split][chunk16][oc72][k 76(pad)]
#define WB_PER  5472                 // 72*76 floats per (split,chunk)
#define WB_SPL  (16 * WB_PER)        // split stride
__device__ float g_wBt[2 * WB_SPL];  // ~700KB

// ================= kernel 0: weight prep =================
__global__ void prep_kernel(const float* __restrict__ w_off,
                            const float* __restrict__ w_dc) {
    int idx = blockIdx.x * blockDim.x + threadIdx.x;
    // deform conv weight transpose [g][k][c][o]
    if (idx < OG * KK * CG * CG) {
        int g = idx / (KK * CG * CG);
        int k = (idx / (CG * CG)) % KK;
        int c = (idx / CG) % CG;
        int o = idx % CG;
        g_wdc_t[idx] = w_dc[((g * CG + o) * CG + c) * KK + k];
    }
    // offset conv B: hi = tf32(w), lo = tf32(w - hi); layout [split][chunk][oc][k76]
    if (idx < 2 * WB_SPL) {
        int split = idx / WB_SPL;
        int rem   = idx % WB_SPL;
        int chunk = rem / WB_PER;
        int e     = rem % WB_PER;
        int oc    = e / 76;
        int kk    = e % 76;
        float val = 0.f;
        if (kk < 72) {
            int tap = kk >> 3;
            int cc  = kk & 7;
            int c   = chunk * 8 + cc;
            float w = w_off[(oc * C_IN + c) * KK + tap];
            uint32_t hb = f2tf32(w);
            if (split == 0) val = __uint_as_float(hb);
            else            val = __uint_as_float(f2tf32(w - __uint_as_float(hb)));
        }
        g_wBt[idx] = val;
    }
}

// ================= kernel 1: offset conv via mma.sync tf32 =================
// Block (h2, n): D[128px][72oc], K=1152 in 16 chunks of 8 ch (9 k8-steps each).
// 4 warps x (2 m16-tiles x 9 n8-tiles). A from f32 strip in smem (bank-clean),
// B hi/lo pre-split in gmem -> smem. 3-term tf32 split per tile.
#define OFFM_THREADS 128
// smem: BsH [72][76] f32, BsL [72][76], strip [8ch][4r][66col] (stride 264)
#define OFFM_F32S (2 * WB_PER + 8 * 264)     // 13056 floats = 52.2KB
__global__ __launch_bounds__(OFFM_THREADS, 4)
void offset_conv_mma(const float* __restrict__ x,
                     const float* __restrict__ b_off) {
    extern __shared__ __align__(16) float sm[];
    float* BsH   = sm;                    // 5472
    float* BsL   = sm + WB_PER;           // 5472
    float* strip = sm + 2 * WB_PER;       // 2112

    const int h2 = blockIdx.x;            // 0..31
    const int n  = blockIdx.y;            // 0..15
    const int b  = n >> 3, d = n & 7;
    const int tid  = threadIdx.x;
    const int w    = tid >> 5;            // warp 0..3
    const int lane = tid & 31;
    const int g    = lane >> 2;           // group id 0..7
    const int t    = lane & 3;            // thread-in-group

    float acc[2][9][4];
#pragma unroll
    for (int mt = 0; mt < 2; mt++)
#pragma unroll
        for (int nt = 0; nt < 9; nt++)
#pragma unroll
            for (int i = 0; i < 4; i++) acc[mt][nt][i] = 0.f;

    const float* xn = x + (((size_t)b * C_IN) * 8 + d) * HW;
    const uint32_t* BsHu = reinterpret_cast<const uint32_t*>(BsH);
    const uint32_t* BsLu = reinterpret_cast<const uint32_t*>(BsL);

    for (int chunk = 0; chunk < 16; chunk++) {
        // copy B hi/lo chunk (pre-padded, straight uint4 copy)
        {
            const uint4* srcH = reinterpret_cast<const uint4*>(g_wBt + (size_t)chunk * WB_PER);
            const uint4* srcL = reinterpret_cast<const uint4*>(g_wBt + (size_t)WB_SPL + (size_t)chunk * WB_PER);
            uint4* dH = reinterpret_cast<uint4*>(BsH);
            uint4* dL = reinterpret_cast<uint4*>(BsL);
            for (int i = tid; i < WB_PER / 4; i += OFFM_THREADS) {
                dH[i] = srcH[i];
                dL[i] = srcL[i];
            }
        }
        // load strip: 8 channels x rows [h2*2-1 .. +2] x cols [-1..64] (zero pad)
        for (int i = tid; i < 8 * 264; i += OFFM_THREADS) {
            int c   = i / 264;
            int rem = i - c * 264;
            int r   = rem / 66;
            int col = rem - r * 66;
            int hin = h2 * 2 - 1 + r;
            int win = col - 1;
            float v = 0.f;
            if (hin >= 0 && hin < HH_ && win >= 0 && win < WW_)
                v = xn[(size_t)(chunk * 8 + c) * (8 * HW) + hin * WW_ + win];
            strip[i] = v;
        }
        __syncthreads();

#pragma unroll 1
        for (int s = 0; s < 9; s++) {          // tap = s
            const int ky = s / 3, kx = s - 3 * ky;
            const int rowblk  = (w >> 1) + ky;
            const int colbase = ((w & 1) << 5) + g + kx;
            // A fragments (hi & lo) for both m-tiles
            uint32_t ah[2][4], al[2][4];
#pragma unroll
            for (int mt = 0; mt < 2; mt++) {
                int base = rowblk * 66 + colbase + mt * 16;
                float v0 = strip[t * 264 + base];
                float v1 = strip[t * 264 + base + 8];
                float v2 = strip[(t + 4) * 264 + base];
                float v3 = strip[(t + 4) * 264 + base + 8];
                ah[mt][0] = f2tf32(v0);
                ah[mt][1] = f2tf32(v1);
                ah[mt][2] = f2tf32(v2);
                ah[mt][3] = f2tf32(v3);
                al[mt][0] = f2tf32(v0 - __uint_as_float(ah[mt][0]));
                al[mt][1] = f2tf32(v1 - __uint_as_float(ah[mt][1]));
                al[mt][2] = f2tf32(v2 - __uint_as_float(ah[mt][2]));
                al[mt][3] = f2tf32(v3 - __uint_as_float(ah[mt][3]));
            }
#pragma unroll
            for (int nt = 0; nt < 9; nt++) {
                int boff = (nt * 8 + g) * 76 + s * 8 + t;
                uint32_t bh0 = BsHu[boff], bh1 = BsHu[boff + 4];
                uint32_t bl0 = BsLu[boff], bl1 = BsLu[boff + 4];
#pragma unroll
                for (int mt = 0; mt < 2; mt++) {
                    mma_tf32(acc[mt][nt], ah[mt], bh0, bh1);
                    mma_tf32(acc[mt][nt], al[mt], bh0, bh1);
                    mma_tf32(acc[mt][nt], ah[mt], bl0, bl1);
                }
            }
        }
        __syncthreads();
    }

    // epilogue: acc -> g_offset[n][oc][px] (+bias)
    float* outp = g_offset + (size_t)n * (OC_OFF * HW) + h2 * 128;
#pragma unroll
    for (int mt = 0; mt < 2; mt++) {
        int px0 = w * 32 + mt * 16 + g;
#pragma unroll
        for (int nt = 0; nt < 9; nt++) {
            int oc0 = nt * 8 + 2 * t;
            float bb0 = b_off[oc0], bb1 = b_off[oc0 + 1];
            outp[(size_t)oc0       * HW + px0    ] = acc[mt][nt][0] + bb0;
            outp[(size_t)(oc0 + 1) * HW + px0    ] = acc[mt][nt][1] + bb1;
            outp[(size_t)oc0       * HW + px0 + 8] = acc[mt][nt][2] + bb0;
            outp[(size_t)(oc0 + 1) * HW + px0 + 8] = acc[mt][nt][3] + bb1;
        }
    }
}

// ================= kernel 2: deformable conv (FFMA2, unchanged) =================
#define DEF_THREADS 128
#define DEF_SMEM_FLOATS (KK * CG * CG + CG * 128)
__global__ __launch_bounds__(DEF_THREADS)
void deform_kernel(const float* __restrict__ x,
                   const float* __restrict__ b_dc) {
    extern __shared__ __align__(16) float smd[];
    float* wdc_s = smd;
    float* samp  = smd + KK * CG * CG;

    const int h2 = blockIdx.x;
    const int g  = blockIdx.y;
    const int n  = blockIdx.z;
    const int b  = n >> 3, d = n & 7;
    const int tid = threadIdx.x;

    for (int i = tid; i < KK * CG * CG; i += DEF_THREADS)
        wdc_s[i] = g_wdc_t[g * (KK * CG * CG) + i];

    const int sp = tid;
    const int sh = h2 * 2 + (sp >> 6);
    const int sw = sp & 63;
    const float* xbase = x + (((size_t)b * C_IN + g * CG) * 8 + d) * HW;
    const float* offb  = g_offset + (size_t)n * (OC_OFF * HW)
                       + (size_t)(g * KK * 2) * HW + sh * WW_ + sw;

    const int ogrp = tid >> 5;
    const int o0   = ogrp * 8;
    const int lane = tid & 31;

    u64 acc2[4][4];
#pragma unroll
    for (int jp = 0; jp < 4; jp++)
#pragma unroll
        for (int i = 0; i < 4; i++) acc2[jp][i] = 0ull;

    __syncthreads();

    for (int k = 0; k < KK; k++) {
        float dy = offb[(size_t)(2 * k) * HW];
        float dx = offb[(size_t)(2 * k + 1) * HW];
        int ky = k / 3, kx = k % 3;
        float py = dy + (float)(sh + ky - 1);
        float px = dx + (float)(sw + kx - 1);
        float y0f = floorf(py), x0f = floorf(px);
        int   y0 = (int)y0f,   x0 = (int)x0f;
        float ly = py - y0f, lx = px - x0f;
        float hy = 1.f - ly, hx = 1.f - lx;
        bool vy0 = (y0 >= 0)  && (y0 < HH_);
        bool vy1 = (y0 >= -1) && (y0 < HH_ - 1);
        bool vx0 = (x0 >= 0)  && (x0 < WW_);
        bool vx1 = (x0 >= -1) && (x0 < WW_ - 1);
        int yc0 = min(max(y0, 0), HH_ - 1), yc1 = min(max(y0 + 1, 0), HH_ - 1);
        int xc0 = min(max(x0, 0), WW_ - 1), xc1 = min(max(x0 + 1, 0), WW_ - 1);
        float w00 = hy * hx * (float)(vy0 && vx0);
        float w01 = hy * lx * (float)(vy0 && vx1);
        float w10 = ly * hx * (float)(vy1 && vx0);
        float w11 = ly * lx * (float)(vy1 && vx1);
        int i00 = yc0 * WW_ + xc0, i01 = yc0 * WW_ + xc1;
        int i10 = yc1 * WW_ + xc0, i11 = yc1 * WW_ + xc1;
#pragma unroll 8
        for (int c = 0; c < CG; c++) {
            const float* xp = xbase + (size_t)c * (8 * HW);
            float v = w00 * __ldg(xp + i00) + w01 * __ldg(xp + i01)
                    + w10 * __ldg(xp + i10) + w11 * __ldg(xp + i11);
            samp[c * 128 + sp] = v;
        }
        __syncthreads();
#pragma unroll
        for (int c = 0; c < CG; c++) {
            u64 sv2[4];
#pragma unroll
            for (int i = 0; i < 4; i++) {
                float sv = samp[c * 128 + lane + 32 * i];
                sv2[i] = pack2(sv, sv);
            }
            const float* wp = &wdc_s[(k * CG + c) * CG + o0];
            u64 wv2[4];
#pragma unroll
            for (int jp = 0; jp < 4; jp++)
                wv2[jp] = *reinterpret_cast<const u64*>(wp + 2 * jp);
#pragma unroll
            for (int jp = 0; jp < 4; jp++)
#pragma unroll
                for (int i = 0; i < 4; i++)
                    fma2(acc2[jp][i], wv2[jp], sv2[i]);
        }
        __syncthreads();
    }

    float* outp = g_tmp + ((size_t)n * OUT_C + g * CG + o0) * HW + h2 * 128;
#pragma unroll
    for (int jp = 0; jp < 4; jp++) {
        float b0 = b_dc[g * CG + o0 + 2 * jp];
        float b1 = b_dc[g * CG + o0 + 2 * jp + 1];
#pragma unroll
        for (int i = 0; i < 4; i++) {
            float lo, hi;
            unpack2(acc2[jp][i], lo, hi);
            int p = lane + 32 * i;
            outp[(size_t)(2 * jp)     * HW + p] = lo + b0;
            outp[(size_t)(2 * jp + 1) * HW + p] = hi + b1;
        }
    }
}

// ================= kernel 3: instance norm + GELU + transpose =================
__global__ __launch_bounds__(256)
void finalize_kernel(float* __restrict__ out) {
    const int c = blockIdx.x;
    const int n = blockIdx.y;
    const int b = n >> 3, d = n & 7;
    const int tid = threadIdx.x;

    const float* tp = g_tmp + ((size_t)n * OUT_C + c) * HW;
    float v[16];
    float s = 0.f, ss = 0.f;
#pragma unroll
    for (int i = 0; i < 16; i++) {
        float t = tp[tid + 256 * i];
        v[i] = t; s += t; ss += t * t;
    }
#pragma unroll
    for (int o = 16; o > 0; o >>= 1) {
        s  += __shfl_down_sync(0xffffffffu, s,  o);
        ss += __shfl_down_sync(0xffffffffu, ss, o);
    }
    __shared__ float s1[8], s2[8];
    __shared__ float mu_s, inv_s;
    int wid = tid >> 5, lane = tid & 31;
    if (lane == 0) { s1[wid] = s; s2[wid] = ss; }
    __syncthreads();
    if (tid == 0) {
        float ts = 0.f, tss = 0.f;
#pragma unroll
        for (int i = 0; i < 8; i++) { ts += s1[i]; tss += s2[i]; }
        float mu  = ts * (1.f / 4096.f);
        float var = tss * (1.f / 4096.f) - mu * mu;
        mu_s  = mu;
        inv_s = rsqrtf(var + 1e-5f);
    }
    __syncthreads();
    float mu = mu_s, inv = inv_s;

    float* op = out + (((size_t)b * OUT_C + c) * 8 + d) * HW;
#pragma unroll
    for (int i = 0; i < 16; i++) {
        float t = (v[i] - mu) * inv;
        op[tid + 256 * i] = 0.5f * t * (1.f + erff(t * 0.70710678118654752f));
    }
}

// ================= launcher =================
extern "C" void kernel_launch(void* const* d_in, const int* in_sizes, int n_in,
                              void* d_out, int out_size) {
    (void)in_sizes; (void)n_in; (void)out_size;
    const float* x     = (const float*)d_in[0];
    const float* w_off = (const float*)d_in[1];
    const float* b_off = (const float*)d_in[2];
    const float* w_dc  = (const float*)d_in[3];
    const float* b_dc  = (const float*)d_in[4];
    float* out = (float*)d_out;

    static int attr_set = 0;
    if (!attr_set) {
        cudaFuncSetAttribute(offset_conv_mma,
                             cudaFuncAttributeMaxDynamicSharedMemorySize,
                             OFFM_F32S * sizeof(float));
        cudaFuncSetAttribute(deform_kernel,
                             cudaFuncAttributeMaxDynamicSharedMemorySize,
                             DEF_SMEM_FLOATS * sizeof(float));
        attr_set = 1;
    }

    prep_kernel<<<(2 * WB_SPL + 255) / 256, 256>>>(w_off, w_dc);

    dim3 gco(32, NB);
    offset_conv_mma<<<gco, OFFM_THREADS, OFFM_F32S * sizeof(float)>>>(x, b_off);

    dim3 gdf(32, OG, NB);
    deform_kernel<<<gdf, DEF_THREADS, DEF_SMEM_FLOATS * sizeof(float)>>>(x, b_dc);

    dim3 gfn(OUT_C, NB);
    finalize_kernel<<<gfn, 256>>>(out);
}

// round 5
// speedup vs baseline: 1.4640x; 1.0968x over previous
#include <cuda_runtime.h>
#include <math.h>
#include <stdint.h>

#define NB     16
#define C_IN   128
#define HH_    64
#define WW_    64
#define HW     4096
#define OC_OFF 72
#define OG     4
#define CG     32
#define OUT_C  128
#define KK     9

typedef unsigned long long u64;

// ---- packed f32x2 helpers (deform conv path) ----
__device__ __forceinline__ u64 pack2(float lo, float hi) {
    u64 r; asm("mov.b64 %0, {%1, %2};" : "=l"(r) : "f"(lo), "f"(hi)); return r;
}
__device__ __forceinline__ void fma2(u64& d, u64 a, u64 b) {
    asm("fma.rn.f32x2 %0, %1, %2, %0;" : "+l"(d) : "l"(a), "l"(b));
}
__device__ __forceinline__ void unpack2(u64 v, float& lo, float& hi) {
    asm("mov.b64 {%0, %1}, %2;" : "=f"(lo), "=f"(hi) : "l"(v));
}

// ---- bf16 helpers (base sm_100 ISA) ----
__device__ __forceinline__ uint32_t bpack(float lo, float hi) {
    uint32_t r; asm("cvt.rn.bf16x2.f32 %0, %1, %2;" : "=r"(r) : "f"(hi), "f"(lo)); return r;
}
// build hi-pack and lo(residual)-pack for 2 floats
__device__ __forceinline__ void bsplit(float v0, float v1, uint32_t& ph, uint32_t& pl) {
    ph = bpack(v0, v1);
    float f0 = __uint_as_float(ph << 16);
    float f1 = __uint_as_float(ph & 0xffff0000u);
    pl = bpack(v0 - f0, v1 - f1);
}
__device__ __forceinline__ void mma_bf16(float* d, const uint32_t* a,
                                         uint32_t b0, uint32_t b1) {
    asm volatile(
        "mma.sync.aligned.m16n8k16.row.col.f32.bf16.bf16.f32 "
        "{%0,%1,%2,%3},{%4,%5,%6,%7},{%8,%9},{%0,%1,%2,%3};"
        : "+f"(d[0]), "+f"(d[1]), "+f"(d[2]), "+f"(d[3])
        : "r"(a[0]), "r"(a[1]), "r"(a[2]), "r"(a[3]), "r"(b0), "r"(b1));
}

// ================= static device scratch =================
__device__ float g_offset[NB * OC_OFF * HW];
__device__ float g_tmp   [NB * OUT_C  * HW];
__device__ float g_wdc_t [OG * KK * CG * CG];            // [g][k][c][o]
// offset conv B fragments, register-layout prepacked:
// [chunk8][s9][nt9][lane32] -> uint4{h0,h1,l0,l1}
__device__ uint4 g_wBf[8 * 9 * 9 * 32];

// ================= kernel 0: weight prep =================
__global__ void prep_kernel(const float* __restrict__ w_off,
                            const float* __restrict__ w_dc) {
    int idx = blockIdx.x * blockDim.x + threadIdx.x;
    // deform conv weight transpose [g][k][c][o]
    if (idx < OG * KK * CG * CG) {
        int g = idx / (KK * CG * CG);
        int k = (idx / (CG * CG)) % KK;
        int c = (idx / CG) % CG;
        int o = idx % CG;
        g_wdc_t[idx] = w_dc[((g * CG + o) * CG + c) * KK + k];
    }
    // offset conv B fragments (bf16 hi/lo) in mma register layout
    if (idx < 8 * 9 * 9 * 32) {
        int chunk = idx / (9 * 9 * 32);
        int rem   = idx % (9 * 9 * 32);
        int s     = rem / (9 * 32);
        int nt    = (rem / 32) % 9;
        int lane  = rem % 32;
        int g = lane >> 2, t = lane & 3;
        int oc = nt * 8 + g;
        // b0: k = 2t, 2t+1 ; b1: k = 2t+8, 2t+9  (k = channel-in-chunk, tap = s)
        float w00 = w_off[(oc * C_IN + chunk * 16 + 2 * t    ) * KK + s];
        float w01 = w_off[(oc * C_IN + chunk * 16 + 2 * t + 1) * KK + s];
        float w10 = w_off[(oc * C_IN + chunk * 16 + 2 * t + 8) * KK + s];
        float w11 = w_off[(oc * C_IN + chunk * 16 + 2 * t + 9) * KK + s];
        uint32_t h0, l0, h1, l1;
        bsplit(w00, w01, h0, l0);
        bsplit(w10, w11, h1, l1);
        g_wBf[idx] = make_uint4(h0, h1, l0, l1);
    }
}

// ================= kernel 1: offset conv via mma.sync bf16 3-split =================
// Block (h2, n): D[128px][72oc], K=1152 in 8 chunks of 16 ch (k = tap*16 + cc).
// 8 warps, 1 m16-tile each. Strip double-buffered; B frags via __ldg(uint4).
#define OFFB_THREADS 256
#define ST_CH  292                 // channel stride (banks: 4*c per channel)
#define ST_ROW 72                  // row stride (data cols at 4..67; 3/68 = const zero)
#define STRIP_F (16 * ST_CH)       // 4672 floats per buffer
__global__ __launch_bounds__(OFFB_THREADS, 3)
void offset_conv_bf16(const float* __restrict__ x,
                      const float* __restrict__ b_off) {
    __shared__ __align__(16) float strip[2][STRIP_F];    // 37.4 KB

    const int h2 = blockIdx.x;            // 0..31
    const int n  = blockIdx.y;            // 0..15
    const int b  = n >> 3, d = n & 7;
    const int tid  = threadIdx.x;
    const int w    = tid >> 5;            // warp = m-tile 0..7
    const int lane = tid & 31;
    const int g    = lane >> 2;
    const int t    = lane & 3;
    const int rowsel  = w >> 2;           // image row within pair
    const int winbase = (w & 3) * 16;     // col base of this m-tile

    float acc[9][4];
#pragma unroll
    for (int nt = 0; nt < 9; nt++)
#pragma unroll
        for (int i = 0; i < 4; i++) acc[nt][i] = 0.f;

    const float* xn = x + (((size_t)b * C_IN) * 8 + d) * HW;

    // zero both buffers once (border cols + invalid rows stay zero forever)
    for (int i = tid; i < 2 * STRIP_F; i += OFFB_THREADS)
        (&strip[0][0])[i] = 0.f;
    __syncthreads();

    // strip loader: 16 ch x 4 rows x 64 cols as float4 (valid rows only)
    auto loadStrip = [&](int buf, int chunk) {
#pragma unroll
        for (int j = 0; j < 4; j++) {
            int f4i = tid + OFFB_THREADS * j;         // 0..1023
            int ch  = f4i >> 6;
            int rem = f4i & 63;
            int r   = rem >> 4;
            int q   = rem & 15;
            int hin = h2 * 2 - 1 + r;
            if (hin >= 0 && hin < HH_) {
                float4 v = __ldg(reinterpret_cast<const float4*>(
                    xn + (size_t)(chunk * 16 + ch) * (8 * HW) + hin * WW_ + 4 * q));
                *reinterpret_cast<float4*>(&strip[buf][ch * ST_CH + r * ST_ROW + 4 + 4 * q]) = v;
            }
        }
    };

    loadStrip(0, 0);
    __syncthreads();

    for (int chunk = 0; chunk < 8; chunk++) {
        const int cur = chunk & 1;
        if (chunk < 7) loadStrip(cur ^ 1, chunk + 1);   // issue next-chunk LDGs early
        const float* S = strip[cur];
        const uint4* Bf = g_wBf + (size_t)chunk * (9 * 9 * 32) + lane;

#pragma unroll
        for (int s = 0; s < 9; s++) {
            const int ky = s / 3, kx = s - 3 * (s / 3);
            const int row  = rowsel + ky;
            const int colb = 3 + winbase + kx;          // strip col of win-1 base
            const int b0i = (2 * t) * ST_CH + row * ST_ROW + colb;
            // 8 strip values (c in {2t,2t+1,2t+8,2t+9} x px in {g, g+8})
            float v00 = S[b0i + g],                 v01 = S[b0i + ST_CH + g];
            float v10 = S[b0i + g + 8],             v11 = S[b0i + ST_CH + g + 8];
            float v20 = S[b0i + 8 * ST_CH + g],     v21 = S[b0i + 9 * ST_CH + g];
            float v30 = S[b0i + 8 * ST_CH + g + 8], v31 = S[b0i + 9 * ST_CH + g + 8];
            uint32_t ah[4], al[4];
            bsplit(v00, v01, ah[0], al[0]);
            bsplit(v10, v11, ah[1], al[1]);
            bsplit(v20, v21, ah[2], al[2]);
            bsplit(v30, v31, ah[3], al[3]);
#pragma unroll
            for (int nt = 0; nt < 9; nt++) {
                uint4 bf = __ldg(Bf + (s * 9 + nt) * 32);
                mma_bf16(acc[nt], ah, bf.x, bf.y);   // hi*hi
                mma_bf16(acc[nt], al, bf.x, bf.y);   // lo*hi
                mma_bf16(acc[nt], ah, bf.z, bf.w);   // hi*lo
            }
        }
        __syncthreads();
    }

    // epilogue: D[px][oc] -> g_offset[n][oc][row*64+win]
    const int imgrow = h2 * 2 + rowsel;
    float* outp = g_offset + (size_t)n * (OC_OFF * HW) + imgrow * WW_ + winbase;
#pragma unroll
    for (int nt = 0; nt < 9; nt++) {
        int oc0 = nt * 8 + 2 * t;
        float bb0 = __ldg(b_off + oc0), bb1 = __ldg(b_off + oc0 + 1);
        outp[(size_t)oc0       * HW + g    ] = acc[nt][0] + bb0;
        outp[(size_t)(oc0 + 1) * HW + g    ] = acc[nt][1] + bb1;
        outp[(size_t)oc0       * HW + g + 8] = acc[nt][2] + bb0;
        outp[(size_t)(oc0 + 1) * HW + g + 8] = acc[nt][3] + bb1;
    }
}

// ================= kernel 2: deformable conv (FFMA2, restructured) =================
// Weights via warp-uniform __ldg (L1 broadcast) — no smem copy.
// samp double-buffered: 1 barrier per tap; offsets prefetched.
#define DEF_THREADS 128
__global__ __launch_bounds__(DEF_THREADS)
void deform_kernel(const float* __restrict__ x,
                   const float* __restrict__ b_dc) {
    __shared__ __align__(16) float samp[2][CG * 128];   // 32 KB

    const int h2 = blockIdx.x;
    const int g  = blockIdx.y;
    const int n  = blockIdx.z;
    const int b  = n >> 3, d = n & 7;
    const int tid = threadIdx.x;

    const int sp = tid;
    const int sh = h2 * 2 + (sp >> 6);
    const int sw = sp & 63;
    const float* xbase = x + (((size_t)b * C_IN + g * CG) * 8 + d) * HW;
    const float* offb  = g_offset + (size_t)n * (OC_OFF * HW)
                       + (size_t)(g * KK * 2) * HW + sh * WW_ + sw;

    const int ogrp = tid >> 5;
    const int o0   = ogrp * 8;
    const int lane = tid & 31;

    // prefetch all 18 offsets (coalesced, deep MLP)
    float dys[KK], dxs[KK];
#pragma unroll
    for (int k = 0; k < KK; k++) {
        dys[k] = __ldg(offb + (size_t)(2 * k) * HW);
        dxs[k] = __ldg(offb + (size_t)(2 * k + 1) * HW);
    }

    u64 acc2[4][4];
#pragma unroll
    for (int jp = 0; jp < 4; jp++)
#pragma unroll
        for (int i = 0; i < 4; i++) acc2[jp][i] = 0ull;

    auto sample = [&](int k, int buf) {
        int ky = k / 3, kx = k - 3 * (k / 3);
        float py = dys[k] + (float)(sh + ky - 1);
        float px = dxs[k] + (float)(sw + kx - 1);
        float y0f = floorf(py), x0f = floorf(px);
        int   y0 = (int)y0f,   x0 = (int)x0f;
        float ly = py - y0f, lx = px - x0f;
        float hy = 1.f - ly, hx = 1.f - lx;
        bool vy0 = (y0 >= 0)  && (y0 < HH_);
        bool vy1 = (y0 >= -1) && (y0 < HH_ - 1);
        bool vx0 = (x0 >= 0)  && (x0 < WW_);
        bool vx1 = (x0 >= -1) && (x0 < WW_ - 1);
        int yc0 = min(max(y0, 0), HH_ - 1), yc1 = min(max(y0 + 1, 0), HH_ - 1);
        int xc0 = min(max(x0, 0), WW_ - 1), xc1 = min(max(x0 + 1, 0), WW_ - 1);
        float w00 = hy * hx * (float)(vy0 && vx0);
        float w01 = hy * lx * (float)(vy0 && vx1);
        float w10 = ly * hx * (float)(vy1 && vx0);
        float w11 = ly * lx * (float)(vy1 && vx1);
        int i00 = yc0 * WW_ + xc0, i01 = yc0 * WW_ + xc1;
        int i10 = yc1 * WW_ + xc0, i11 = yc1 * WW_ + xc1;
#pragma unroll 8
        for (int c = 0; c < CG; c++) {
            const float* xp = xbase + (size_t)c * (8 * HW);
            float v = w00 * __ldg(xp + i00) + w01 * __ldg(xp + i01)
                    + w10 * __ldg(xp + i10) + w11 * __ldg(xp + i11);
            samp[buf][c * 128 + sp] = v;
        }
    };

    auto gemm = [&](int k, int buf) {
        const u64* wq = reinterpret_cast<const u64*>(
            g_wdc_t + ((size_t)(g * KK + k) * CG) * CG + o0);
#pragma unroll
        for (int c = 0; c < CG; c++) {
            u64 sv2[4];
#pragma unroll
            for (int i = 0; i < 4; i++) {
                float sv = samp[buf][c * 128 + lane + 32 * i];
                sv2[i] = pack2(sv, sv);
            }
            u64 wv2[4];
#pragma unroll
            for (int jp = 0; jp < 4; jp++)
                wv2[jp] = __ldg(wq + c * (CG / 2) + jp);   // warp-uniform
#pragma unroll
            for (int jp = 0; jp < 4; jp++)
#pragma unroll
                for (int i = 0; i < 4; i++)
                    fma2(acc2[jp][i], wv2[jp], sv2[i]);
        }
    };

    sample(0, 0);
    __syncthreads();
#pragma unroll 1
    for (int k = 1; k < KK; k++) {
        sample(k, k & 1);          // LDGs issue first, overlap gemm below
        gemm(k - 1, (k - 1) & 1);
        __syncthreads();
    }
    gemm(KK - 1, (KK - 1) & 1);

    float* outp = g_tmp + ((size_t)n * OUT_C + g * CG + o0) * HW + h2 * 128;
#pragma unroll
    for (int jp = 0; jp < 4; jp++) {
        float b0 = b_dc[g * CG + o0 + 2 * jp];
        float b1 = b_dc[g * CG + o0 + 2 * jp + 1];
#pragma unroll
        for (int i = 0; i < 4; i++) {
            float lo, hi;
            unpack2(acc2[jp][i], lo, hi);
            int p = lane + 32 * i;
            outp[(size_t)(2 * jp)     * HW + p] = lo + b0;
            outp[(size_t)(2 * jp + 1) * HW + p] = hi + b1;
        }
    }
}

// ================= kernel 3: instance norm + GELU + transpose =================
__global__ __launch_bounds__(256)
void finalize_kernel(float* __restrict__ out) {
    const int c = blockIdx.x;
    const int n = blockIdx.y;
    const int b = n >> 3, d = n & 7;
    const int tid = threadIdx.x;

    const float* tp = g_tmp + ((size_t)n * OUT_C + c) * HW;
    float v[16];
    float s = 0.f, ss = 0.f;
#pragma unroll
    for (int i = 0; i < 16; i++) {
        float t = tp[tid + 256 * i];
        v[i] = t; s += t; ss += t * t;
    }
#pragma unroll
    for (int o = 16; o > 0; o >>= 1) {
        s  += __shfl_down_sync(0xffffffffu, s,  o);
        ss += __shfl_down_sync(0xffffffffu, ss, o);
    }
    __shared__ float s1[8], s2[8];
    __shared__ float mu_s, inv_s;
    int wid = tid >> 5, lane = tid & 31;
    if (lane == 0) { s1[wid] = s; s2[wid] = ss; }
    __syncthreads();
    if (tid == 0) {
        float ts = 0.f, tss = 0.f;
#pragma unroll
        for (int i = 0; i < 8; i++) { ts += s1[i]; tss += s2[i]; }
        float mu  = ts * (1.f / 4096.f);
        float var = tss * (1.f / 4096.f) - mu * mu;
        mu_s  = mu;
        inv_s = rsqrtf(var + 1e-5f);
    }
    __syncthreads();
    float mu = mu_s, inv = inv_s;

    float* op = out + (((size_t)b * OUT_C + c) * 8 + d) * HW;
#pragma unroll
    for (int i = 0; i < 16; i++) {
        float t = (v[i] - mu) * inv;
        op[tid + 256 * i] = 0.5f * t * (1.f + erff(t * 0.70710678118654752f));
    }
}

// ================= launcher =================
extern "C" void kernel_launch(void* const* d_in, const int* in_sizes, int n_in,
                              void* d_out, int out_size) {
    (void)in_sizes; (void)n_in; (void)out_size;
    const float* x     = (const float*)d_in[0];
    const float* w_off = (const float*)d_in[1];
    const float* b_off = (const float*)d_in[2];
    const float* w_dc  = (const float*)d_in[3];
    const float* b_dc  = (const float*)d_in[4];
    float* out = (float*)d_out;

    prep_kernel<<<(OG * KK * CG * CG + 255) / 256, 256>>>(w_off, w_dc);

    dim3 gco(32, NB);
    offset_conv_bf16<<<gco, OFFB_THREADS>>>(x, b_off);

    dim3 gdf(32, OG, NB);
    deform_kernel<<<gdf, DEF_THREADS>>>(x, b_dc);

    dim3 gfn(OUT_C, NB);
    finalize_kernel<<<gfn, 256>>>(out);
}